// round 13
// baseline (speedup 1.0000x reference)
#include <cuda_runtime.h>
#include <cuda_fp16.h>
#include <cstdint>

#define RESV 0.16f
#define XMINV (-51.2f)
#define YMINV (-51.2f)
#define EPSV 1e-5f
#define NEGV (-1.0e9f)
#define NEGH2 0xFBFFFBFFu   // fp16x2 {-65504,-65504}

// ---------------- folded weights + fragment tables ----------------
__device__ float4 g_w1pack[64];    // {Wx,Wy,Wz,Wr}*a1 per channel
__device__ float4 g_k1pack[64];    // {b1f, Wxc, Wyc, Wzm}
__device__ float2 g_b2p[32];       // bias pairs (c=2i, 2i+1)
__device__ float  g_a2[64];
__device__ unsigned g_W1frag[256]; // [n-tile 0..7][lane] m16n8k8 B frags
__device__ uint2    g_W2frag[1024];// [(n-tile*4+k-tile)][lane] m16n8k16 B frags
__device__ int g_is64;

__device__ __forceinline__ unsigned pkf(float lo, float hi) {
    unsigned r;
    asm("cvt.rn.f16x2.f32 %0, %1, %2;" : "=r"(r) : "f"(hi), "f"(lo));
    return r;
}

__global__ void prep_kernel(const float* __restrict__ W1, const float* __restrict__ b1,
                            const float* __restrict__ g1, const float* __restrict__ beta1,
                            const float* __restrict__ m1, const float* __restrict__ v1,
                            const float* __restrict__ W2, const float* __restrict__ b2,
                            const float* __restrict__ g2, const float* __restrict__ beta2,
                            const float* __restrict__ m2, const float* __restrict__ v2,
                            const unsigned* __restrict__ coords_raw, int n_words) {
    int tid = threadIdx.x;  // 128 threads
    if (tid == 0) g_is64 = 1;
    __syncthreads();
    int nz = 0;
    for (int i = 2 * tid + 1; i < n_words; i += 256) nz |= (coords_raw[i] != 0u);
    if (nz) g_is64 = 0;

    if (tid < 64) {
        int c = tid;
        float a1 = g1[c] * rsqrtf(v1[c] + EPSV);
        float w0 = W1[0*64+c], w1 = W1[1*64+c], w2v = W1[2*64+c];
        float w3 = W1[3*64+c], w4 = W1[4*64+c], w5 = W1[5*64+c];
        float w6 = W1[6*64+c], w7 = W1[7*64+c], w8 = W1[8*64+c];
        g_w1pack[c] = make_float4((w0+w4+w7)*a1, (w1+w5+w8)*a1, (w2v+w6)*a1, w3*a1);
        g_k1pack[c] = make_float4((b1[c]-m1[c])*a1 + beta1[c], (w4+w7)*a1, (w5+w8)*a1, w6*a1);
        float a2 = g2[c] * rsqrtf(v2[c] + EPSV);
        g_a2[c] = a2;
        ((float*)g_b2p)[c] = (b2[c] - m2[c]) * a2 + beta2[c];
    }
    __syncthreads();

    // W1 B-fragments (m16n8k8): n-tile t, lane l -> n=8t+l/4, k0=2(l%4)
    for (int idx = tid; idx < 256; idx += 128) {
        int t = idx >> 5, l = idx & 31;
        int n = 8 * t + (l >> 2), k0 = (l & 3) * 2;
        float4 wp = g_w1pack[n];
        float4 kp = g_k1pack[n];
        float row[8] = {wp.x, wp.y, wp.z, wp.w, -kp.y, -kp.z, -kp.w, kp.x};
        g_W1frag[idx] = pkf(row[k0], row[k0 + 1]);
    }
    // W2 B-fragments (m16n8k16): tile=(t2*4+ks), lane l -> n=8t2+l/4, j=l%4
    for (int idx = tid; idx < 1024; idx += 128) {
        int tile = idx >> 5, l = idx & 31;
        int t2 = tile >> 2, ks = tile & 3;
        int c = 8 * t2 + (l >> 2), j = l & 3;
        float a2v = g_a2[c];
        int k0 = 16 * ks + 2 * j;
        unsigned b0 = pkf(W2[k0 * 64 + c] * a2v,        W2[(k0 + 1) * 64 + c] * a2v);
        unsigned b1v = pkf(W2[(k0 + 8) * 64 + c] * a2v, W2[(k0 + 9) * 64 + c] * a2v);
        g_W2frag[idx] = make_uint2(b0, b1v);
    }
}

// ---------------- helpers ----------------
__device__ __forceinline__ uint32_t smem_u32(const void* p) {
    uint32_t a;
    asm("{ .reg .u64 t; cvta.to.shared.u64 t, %1; cvt.u32.u64 %0, t; }" : "=r"(a) : "l"(p));
    return a;
}
__device__ __forceinline__ void ldm4(unsigned* r, uint32_t a) {
    asm volatile("ldmatrix.sync.aligned.m8n8.x4.shared.b16 {%0,%1,%2,%3}, [%4];"
        : "=r"(r[0]), "=r"(r[1]), "=r"(r[2]), "=r"(r[3]) : "r"(a));
}
__device__ __forceinline__ void mma_k8_z(float* d, const unsigned* a, unsigned b0) {
    asm("mma.sync.aligned.m16n8k8.row.col.f32.f16.f16.f32 "
        "{%0,%1,%2,%3}, {%4,%5}, {%6}, {%7,%8,%9,%10};"
        : "=f"(d[0]), "=f"(d[1]), "=f"(d[2]), "=f"(d[3])
        : "r"(a[0]), "r"(a[1]), "r"(b0),
          "f"(0.f), "f"(0.f), "f"(0.f), "f"(0.f));
}
__device__ __forceinline__ void mma_f16_z(float* d, const unsigned* a, unsigned b0, unsigned b1) {
    asm("mma.sync.aligned.m16n8k16.row.col.f32.f16.f16.f32 "
        "{%0,%1,%2,%3}, {%4,%5,%6,%7}, {%8,%9}, {%10,%11,%12,%13};"
        : "=f"(d[0]), "=f"(d[1]), "=f"(d[2]), "=f"(d[3])
        : "r"(a[0]), "r"(a[1]), "r"(a[2]), "r"(a[3]), "r"(b0), "r"(b1),
          "f"(0.f), "f"(0.f), "f"(0.f), "f"(0.f));
}
__device__ __forceinline__ void mma_f16(float* c, const unsigned* a, unsigned b0, unsigned b1) {
    asm("mma.sync.aligned.m16n8k16.row.col.f32.f16.f16.f32 "
        "{%0,%1,%2,%3}, {%4,%5,%6,%7}, {%8,%9}, {%0,%1,%2,%3};"
        : "+f"(c[0]), "+f"(c[1]), "+f"(c[2]), "+f"(c[3])
        : "r"(a[0]), "r"(a[1]), "r"(a[2]), "r"(a[3]), "r"(b0), "r"(b1));
}
__device__ __forceinline__ unsigned hmax2(unsigned a, unsigned b) {
    unsigned r;
    asm("max.f16x2 %0, %1, %2;" : "=r"(r) : "r"(a), "r"(b));
    return r;
}

__device__ __forceinline__ void load_pillar(int p, int is64,
        const void* __restrict__ coords_raw, const void* __restrict__ npts_raw,
        const float4* __restrict__ pillars, int lane,
        int& np, float& xc, float& yc, float4& pt) {
    long long rw, cl;
    if (is64) {
        np = (int)((const long long*)npts_raw)[p];
        rw = ((const long long*)coords_raw)[2 * p];
        cl = ((const long long*)coords_raw)[2 * p + 1];
    } else {
        np = ((const int*)npts_raw)[p];
        rw = (long long)((const int*)coords_raw)[2 * p];
        cl = (long long)((const int*)coords_raw)[2 * p + 1];
    }
    xc = ((float)cl + 0.5f) * RESV + XMINV;
    yc = ((float)rw + 0.5f) * RESV + YMINV;
    pt = pillars[(size_t)p * 32 + lane];
}

__global__ void __launch_bounds__(128, 5)
pfn_main(const float4* __restrict__ pillars,
         const void* __restrict__ coords_raw,
         const void* __restrict__ npts_raw,
         float* __restrict__ out, int P) {
    __shared__ uint4 s_feat[128];    // 4 warps x 32 rows x 16B (2KB)
    __shared__ float2 s_b2p[32];
    __shared__ uint2 s_W2[1024];     // W2 fragments, [tile][lane] (8KB)
    __shared__ uint4 s_A2[4][8][32]; // A2 frags: [warp][mt*4+ks][lane] (16KB)
    const int tid = threadIdx.x;
    const int wid = tid >> 5;
    const int lane = tid & 31;
    const int is64 = g_is64;

    if (tid < 32) s_b2p[tid] = g_b2p[tid];
    for (int i = tid; i < 1024; i += 128) s_W2[i] = g_W2frag[i];

    // W1 fragments stay in registers (8 regs)
    unsigned W1B[8];
#pragma unroll
    for (int t = 0; t < 8; t++) W1B[t] = g_W1frag[t * 32 + lane];

    const uint32_t featAddr = smem_u32(s_feat + (wid << 5)) + (uint32_t)lane * 16u;
    uint4* myfeat = s_feat + (wid << 5) + lane;
    const uint2* w2p = s_W2 + lane;        // tile i at w2p[i*32]
    uint4* a2p = &s_A2[wid][0][lane];      // slot j at a2p[j*32]
    const int rbase = lane >> 2;
    const int stride = gridDim.x * 4;
    __syncthreads();  // s_b2p / s_W2 ready

    int p = blockIdx.x * 4 + wid;
    int np = 0; float xc = 0.f, yc = 0.f; float4 pt = make_float4(0.f, 0.f, 0.f, 0.f);
    if (p < P) load_pillar(p, is64, coords_raw, npts_raw, pillars, lane, np, xc, yc, pt);

    while (p < P) {
        // ---- capture current, issue prefetch for next ----
        const int cp = p, cnp = np;
        const float cxc = xc, cyc = yc;
        const float4 cpt = pt;
        p += stride;
        if (p < P) load_pillar(p, is64, coords_raw, npts_raw, pillars, lane, np, xc, yc, pt);

        // ---- empty pillar: output all NEGV, skip compute (warp-uniform) ----
        if (cnp == 0) {
            *(float2*)(out + (size_t)cp * 64 + 2 * lane) = make_float2(NEGV, NEGV);
            continue;
        }
        const bool big = (cnp > 16);  // warp-uniform: rows 16..31 live?

        // ---- zmean ----
        float zs = (lane < cnp) ? cpt.z : 0.f;
#pragma unroll
        for (int o = 16; o; o >>= 1) zs += __shfl_xor_sync(0xffffffffu, zs, o);
        const float zm = zs / (float)cnp;

        // ---- feat row (fp16): [x,y,z,r,xc,yc,zm,1] ----
        *myfeat = make_uint4(pkf(cpt.x, cpt.y), pkf(cpt.z, cpt.w),
                             pkf(cxc, cyc), pkf(zm, 1.0f));
        __syncwarp();
        unsigned A1[4];
        ldm4(A1, featAddr);
        __syncwarp();

        // ---- layer 1 via m16n8k8; pack per-(mt,ks) fragment -> one STS.128 ----
        // slot = mt*4 + s, s = hh*2 + ntp; thread-private smem roundtrip (no sync)
#pragma unroll
        for (int hh = 0; hh < 2; hh++)
#pragma unroll
            for (int ntp = 0; ntp < 2; ntp++) {
                float Ce[4], Co[4];
                mma_k8_z(Ce, &A1[0], W1B[hh * 4 + 2 * ntp]);
                mma_k8_z(Co, &A1[0], W1B[hh * 4 + 2 * ntp + 1]);
                uint4 v;
                v.x = pkf(fmaxf(Ce[0], 0.f), fmaxf(Ce[1], 0.f));
                v.y = pkf(fmaxf(Ce[2], 0.f), fmaxf(Ce[3], 0.f));
                v.z = pkf(fmaxf(Co[0], 0.f), fmaxf(Co[1], 0.f));
                v.w = pkf(fmaxf(Co[2], 0.f), fmaxf(Co[3], 0.f));
                a2p[(hh * 2 + ntp) * 32] = v;
            }
        if (big) {
#pragma unroll
            for (int hh = 0; hh < 2; hh++)
#pragma unroll
                for (int ntp = 0; ntp < 2; ntp++) {
                    float Ce[4], Co[4];
                    mma_k8_z(Ce, &A1[2], W1B[hh * 4 + 2 * ntp]);
                    mma_k8_z(Co, &A1[2], W1B[hh * 4 + 2 * ntp + 1]);
                    uint4 v;
                    v.x = pkf(fmaxf(Ce[0], 0.f), fmaxf(Ce[1], 0.f));
                    v.y = pkf(fmaxf(Ce[2], 0.f), fmaxf(Ce[3], 0.f));
                    v.z = pkf(fmaxf(Co[0], 0.f), fmaxf(Co[1], 0.f));
                    v.w = pkf(fmaxf(Co[2], 0.f), fmaxf(Co[3], 0.f));
                    a2p[(4 + hh * 2 + ntp) * 32] = v;
                }
        }

        // ---- layer 2 via m16n8k16 (A frags reloaded from smem) + epilogue ----
        const bool v0 = (rbase < cnp), v1 = (rbase + 8 < cnp);
        const bool v2 = (rbase + 16 < cnp), v3 = (rbase + 24 < cnp);
#pragma unroll
        for (int hh2 = 0; hh2 < 2; hh2++) {
            float C2a[4][4], C2b[4][4];
            {
                uint4 a = a2p[0];
#pragma unroll
                for (int nt = 0; nt < 4; nt++) {
                    uint2 b = w2p[((hh2 * 4 + nt) * 4) * 32];
                    mma_f16_z(C2a[nt], (const unsigned*)&a, b.x, b.y);
                }
            }
#pragma unroll
            for (int ks = 1; ks < 4; ks++) {
                uint4 a = a2p[ks * 32];
#pragma unroll
                for (int nt = 0; nt < 4; nt++) {
                    uint2 b = w2p[((hh2 * 4 + nt) * 4 + ks) * 32];
                    mma_f16(C2a[nt], (const unsigned*)&a, b.x, b.y);
                }
            }
            if (big) {
                {
                    uint4 a = a2p[4 * 32];
#pragma unroll
                    for (int nt = 0; nt < 4; nt++) {
                        uint2 b = w2p[((hh2 * 4 + nt) * 4) * 32];
                        mma_f16_z(C2b[nt], (const unsigned*)&a, b.x, b.y);
                    }
                }
#pragma unroll
                for (int ks = 1; ks < 4; ks++) {
                    uint4 a = a2p[(4 + ks) * 32];
#pragma unroll
                    for (int nt = 0; nt < 4; nt++) {
                        uint2 b = w2p[((hh2 * 4 + nt) * 4 + ks) * 32];
                        mma_f16(C2b[nt], (const unsigned*)&a, b.x, b.y);
                    }
                }
            }
#pragma unroll
            for (int nt = 0; nt < 4; nt++) {
                unsigned best = NEGH2;
                unsigned m0 = pkf(C2a[nt][0], C2a[nt][1]);
                unsigned m1 = pkf(C2a[nt][2], C2a[nt][3]);
                if (v0) best = hmax2(best, m0);
                if (v1) best = hmax2(best, m1);
                if (big) {
                    unsigned m2v = pkf(C2b[nt][0], C2b[nt][1]);
                    unsigned m3 = pkf(C2b[nt][2], C2b[nt][3]);
                    if (v2) best = hmax2(best, m2v);
                    if (v3) best = hmax2(best, m3);
                }
#pragma unroll
                for (int off = 4; off <= 16; off <<= 1)
                    best = hmax2(best, __shfl_xor_sync(0xffffffffu, best, off));
                if (lane < 4) {
                    int t2 = hh2 * 4 + nt;
                    float2 bv = s_b2p[t2 * 4 + lane];
                    __half2 bh = *reinterpret_cast<__half2*>(&best);
                    float2 res;
                    res.x = fmaxf(__low2float(bh) + bv.x, 0.f);
                    res.y = fmaxf(__high2float(bh) + bv.y, 0.f);
                    *(float2*)(out + (size_t)cp * 64 + t2 * 8 + 2 * lane) = res;
                }
            }
        }
        __syncwarp();  // protect s_feat reuse across iterations
    }
}

extern "C" void kernel_launch(void* const* d_in, const int* in_sizes, int n_in,
                              void* d_out, int out_size) {
    const float* pillars = (const float*)d_in[0];
    const void*  coords  = d_in[1];
    const void*  npts    = d_in[2];
    const float* W1 = (const float*)d_in[3];
    const float* b1 = (const float*)d_in[4];
    const float* g1 = (const float*)d_in[5];
    const float* be1 = (const float*)d_in[6];
    const float* m1 = (const float*)d_in[7];
    const float* v1 = (const float*)d_in[8];
    const float* W2 = (const float*)d_in[9];
    const float* b2 = (const float*)d_in[10];
    const float* g2 = (const float*)d_in[11];
    const float* be2 = (const float*)d_in[12];
    const float* m2 = (const float*)d_in[13];
    const float* v2 = (const float*)d_in[14];

    int P = in_sizes[0] / 128;
    int n_words = 2 * P < 4096 ? 2 * P : 4096;

    prep_kernel<<<1, 128>>>(W1, b1, g1, be1, m1, v1, W2, b2, g2, be2, m2, v2,
                            (const unsigned*)coords, n_words);

    int grid = 5 * 152;
    int need = (P + 3) / 4;
    if (grid > need) grid = need;
    if (grid < 1) grid = 1;
    pfn_main<<<grid, 128>>>((const float4*)pillars, coords, npts, (float*)d_out, P);
}

// round 15
// speedup vs baseline: 1.3023x; 1.3023x over previous
#include <cuda_runtime.h>
#include <cuda_fp16.h>
#include <cstdint>

#define RESV 0.16f
#define XMINV (-51.2f)
#define YMINV (-51.2f)
#define EPSV 1e-5f
#define NEGV (-1.0e9f)
#define NEGH2 0xFBFFFBFFu   // fp16x2 {-65504,-65504}

// ---------------- folded weights + fragment tables ----------------
__device__ float4 g_w1pack[64];    // {Wx,Wy,Wz,Wr}*a1 per channel
__device__ float4 g_k1pack[64];    // {b1f, Wxc, Wyc, Wzm}
__device__ float2 g_b2p[32];       // bias pairs (c=2i, 2i+1)
__device__ float  g_a2[64];
__device__ unsigned g_W1frag[256]; // [n-tile 0..7][lane] m16n8k8 B frags
__device__ uint2    g_W2frag[1024];// [(n-tile*4+k-tile)][lane] m16n8k16 B frags
__device__ int g_is64;

__device__ __forceinline__ unsigned pkf(float lo, float hi) {
    unsigned r;
    asm("cvt.rn.f16x2.f32 %0, %1, %2;" : "=r"(r) : "f"(hi), "f"(lo));
    return r;
}

__global__ void prep_kernel(const float* __restrict__ W1, const float* __restrict__ b1,
                            const float* __restrict__ g1, const float* __restrict__ beta1,
                            const float* __restrict__ m1, const float* __restrict__ v1,
                            const float* __restrict__ W2, const float* __restrict__ b2,
                            const float* __restrict__ g2, const float* __restrict__ beta2,
                            const float* __restrict__ m2, const float* __restrict__ v2,
                            const unsigned* __restrict__ coords_raw, int n_words) {
    int tid = threadIdx.x;  // 128 threads
    if (tid == 0) g_is64 = 1;
    __syncthreads();
    int nz = 0;
    for (int i = 2 * tid + 1; i < n_words; i += 256) nz |= (coords_raw[i] != 0u);
    if (nz) g_is64 = 0;

    if (tid < 64) {
        int c = tid;
        float a1 = g1[c] * rsqrtf(v1[c] + EPSV);
        float w0 = W1[0*64+c], w1 = W1[1*64+c], w2v = W1[2*64+c];
        float w3 = W1[3*64+c], w4 = W1[4*64+c], w5 = W1[5*64+c];
        float w6 = W1[6*64+c], w7 = W1[7*64+c], w8 = W1[8*64+c];
        g_w1pack[c] = make_float4((w0+w4+w7)*a1, (w1+w5+w8)*a1, (w2v+w6)*a1, w3*a1);
        g_k1pack[c] = make_float4((b1[c]-m1[c])*a1 + beta1[c], (w4+w7)*a1, (w5+w8)*a1, w6*a1);
        float a2 = g2[c] * rsqrtf(v2[c] + EPSV);
        g_a2[c] = a2;
        ((float*)g_b2p)[c] = (b2[c] - m2[c]) * a2 + beta2[c];
    }
    __syncthreads();

    // W1 B-fragments (m16n8k8): n-tile t, lane l -> n=8t+l/4, k0=2(l%4)
    for (int idx = tid; idx < 256; idx += 128) {
        int t = idx >> 5, l = idx & 31;
        int n = 8 * t + (l >> 2), k0 = (l & 3) * 2;
        float4 wp = g_w1pack[n];
        float4 kp = g_k1pack[n];
        float row[8] = {wp.x, wp.y, wp.z, wp.w, -kp.y, -kp.z, -kp.w, kp.x};
        g_W1frag[idx] = pkf(row[k0], row[k0 + 1]);
    }
    // W2 B-fragments (m16n8k16): tile=(t2*4+ks), lane l -> n=8t2+l/4, j=l%4
    for (int idx = tid; idx < 1024; idx += 128) {
        int tile = idx >> 5, l = idx & 31;
        int t2 = tile >> 2, ks = tile & 3;
        int c = 8 * t2 + (l >> 2), j = l & 3;
        float a2v = g_a2[c];
        int k0 = 16 * ks + 2 * j;
        unsigned b0 = pkf(W2[k0 * 64 + c] * a2v,        W2[(k0 + 1) * 64 + c] * a2v);
        unsigned b1v = pkf(W2[(k0 + 8) * 64 + c] * a2v, W2[(k0 + 9) * 64 + c] * a2v);
        g_W2frag[idx] = make_uint2(b0, b1v);
    }
}

// ---------------- helpers ----------------
__device__ __forceinline__ uint32_t smem_u32(const void* p) {
    uint32_t a;
    asm("{ .reg .u64 t; cvta.to.shared.u64 t, %1; cvt.u32.u64 %0, t; }" : "=r"(a) : "l"(p));
    return a;
}
__device__ __forceinline__ void ldm4(unsigned* r, uint32_t a) {
    asm volatile("ldmatrix.sync.aligned.m8n8.x4.shared.b16 {%0,%1,%2,%3}, [%4];"
        : "=r"(r[0]), "=r"(r[1]), "=r"(r[2]), "=r"(r[3]) : "r"(a));
}
__device__ __forceinline__ void mma_k8_z(float* d, const unsigned* a, unsigned b0) {
    asm("mma.sync.aligned.m16n8k8.row.col.f32.f16.f16.f32 "
        "{%0,%1,%2,%3}, {%4,%5}, {%6}, {%7,%8,%9,%10};"
        : "=f"(d[0]), "=f"(d[1]), "=f"(d[2]), "=f"(d[3])
        : "r"(a[0]), "r"(a[1]), "r"(b0),
          "f"(0.f), "f"(0.f), "f"(0.f), "f"(0.f));
}
__device__ __forceinline__ void mma_f16_z(float* d, const unsigned* a, unsigned b0, unsigned b1) {
    asm("mma.sync.aligned.m16n8k16.row.col.f32.f16.f16.f32 "
        "{%0,%1,%2,%3}, {%4,%5,%6,%7}, {%8,%9}, {%10,%11,%12,%13};"
        : "=f"(d[0]), "=f"(d[1]), "=f"(d[2]), "=f"(d[3])
        : "r"(a[0]), "r"(a[1]), "r"(a[2]), "r"(a[3]), "r"(b0), "r"(b1),
          "f"(0.f), "f"(0.f), "f"(0.f), "f"(0.f));
}
__device__ __forceinline__ void mma_f16(float* c, const unsigned* a, unsigned b0, unsigned b1) {
    asm("mma.sync.aligned.m16n8k16.row.col.f32.f16.f16.f32 "
        "{%0,%1,%2,%3}, {%4,%5,%6,%7}, {%8,%9}, {%0,%1,%2,%3};"
        : "+f"(c[0]), "+f"(c[1]), "+f"(c[2]), "+f"(c[3])
        : "r"(a[0]), "r"(a[1]), "r"(a[2]), "r"(a[3]), "r"(b0), "r"(b1));
}
__device__ __forceinline__ unsigned hmax2(unsigned a, unsigned b) {
    unsigned r;
    asm("max.f16x2 %0, %1, %2;" : "=r"(r) : "r"(a), "r"(b));
    return r;
}

__device__ __forceinline__ void load_pillar(int p, int is64,
        const void* __restrict__ coords_raw, const void* __restrict__ npts_raw,
        const float4* __restrict__ pillars, int lane,
        int& np, float& xc, float& yc, float4& pt) {
    long long rw, cl;
    if (is64) {
        np = (int)((const long long*)npts_raw)[p];
        rw = ((const long long*)coords_raw)[2 * p];
        cl = ((const long long*)coords_raw)[2 * p + 1];
    } else {
        np = ((const int*)npts_raw)[p];
        rw = (long long)((const int*)coords_raw)[2 * p];
        cl = (long long)((const int*)coords_raw)[2 * p + 1];
    }
    xc = ((float)cl + 0.5f) * RESV + XMINV;
    yc = ((float)rw + 0.5f) * RESV + YMINV;
    pt = pillars[(size_t)p * 32 + lane];
}

// merged-tile epilogue: 8 shfl per hh2 instead of 12; stores from lanes 0..7
template <bool BIG>
__device__ __forceinline__ void epilogue(const float C2a[4][4], const float C2b[4][4],
        bool v0, bool v1, bool v2, bool v3, int lane, int hh2,
        const float2* s_b2p, float* __restrict__ out, int cp) {
    unsigned s[4];
#pragma unroll
    for (int nt = 0; nt < 4; nt++) {
        unsigned best = NEGH2;
        unsigned m0 = pkf(C2a[nt][0], C2a[nt][1]);
        unsigned m1 = pkf(C2a[nt][2], C2a[nt][3]);
        if (v0) best = hmax2(best, m0);
        if (v1) best = hmax2(best, m1);
        if (BIG) {
            unsigned m2v = pkf(C2b[nt][0], C2b[nt][1]);
            unsigned m3 = pkf(C2b[nt][2], C2b[nt][3]);
            if (v2) best = hmax2(best, m2v);
            if (v3) best = hmax2(best, m3);
        }
        s[nt] = hmax2(best, __shfl_xor_sync(0xffffffffu, best, 4));
    }
    const bool hi = (lane & 4) != 0;
    unsigned z0 = hi ? s[1] : s[0];
    unsigned z1 = hi ? s[3] : s[2];
    z0 = hmax2(z0, __shfl_xor_sync(0xffffffffu, z0, 8));
    z1 = hmax2(z1, __shfl_xor_sync(0xffffffffu, z1, 8));
    z0 = hmax2(z0, __shfl_xor_sync(0xffffffffu, z0, 16));
    z1 = hmax2(z1, __shfl_xor_sync(0xffffffffu, z1, 16));
    if (lane < 8) {
        int tb = hh2 * 4 + (lane >> 2);       // z0 tile; z1 tile = tb+2
        int cidx = lane & 3;
        __half2 h0 = *reinterpret_cast<__half2*>(&z0);
        __half2 h1 = *reinterpret_cast<__half2*>(&z1);
        float2 bv0 = s_b2p[tb * 4 + cidx];
        float2 bv1 = s_b2p[(tb + 2) * 4 + cidx];
        float2 r0, r1;
        r0.x = fmaxf(__low2float(h0) + bv0.x, 0.f);
        r0.y = fmaxf(__high2float(h0) + bv0.y, 0.f);
        r1.x = fmaxf(__low2float(h1) + bv1.x, 0.f);
        r1.y = fmaxf(__high2float(h1) + bv1.y, 0.f);
        *(float2*)(out + (size_t)cp * 64 + tb * 8 + 2 * cidx) = r0;
        *(float2*)(out + (size_t)cp * 64 + (tb + 2) * 8 + 2 * cidx) = r1;
    }
}

__global__ void __launch_bounds__(128, 4)
pfn_main(const float4* __restrict__ pillars,
         const void* __restrict__ coords_raw,
         const void* __restrict__ npts_raw,
         float* __restrict__ out, int P) {
    __shared__ uint4 s_feat[128];    // 4 warps x 32 rows x 16B
    __shared__ float2 s_b2p[32];
    __shared__ uint2 s_W2[1024];     // W2 fragments, [tile][lane] layout (8KB)
    const int tid = threadIdx.x;
    const int wid = tid >> 5;
    const int lane = tid & 31;
    const int is64 = g_is64;

    if (tid < 32) s_b2p[tid] = g_b2p[tid];
    for (int i = tid; i < 1024; i += 128) s_W2[i] = g_W2frag[i];

    // W1 fragments stay in registers (8 regs)
    unsigned W1B[8];
#pragma unroll
    for (int t = 0; t < 8; t++) W1B[t] = g_W1frag[t * 32 + lane];

    const uint32_t featAddr = smem_u32(s_feat + (wid << 5)) + (uint32_t)lane * 16u;
    uint4* myfeat = s_feat + (wid << 5) + lane;
    const uint2* w2p = s_W2 + lane;   // tile i at w2p[i*32]
    const int rbase = lane >> 2;
    const int stride = gridDim.x * 4;
    __syncthreads();  // s_b2p / s_W2 ready

    int p = blockIdx.x * 4 + wid;
    int np = 0; float xc = 0.f, yc = 0.f; float4 pt = make_float4(0.f, 0.f, 0.f, 0.f);
    if (p < P) load_pillar(p, is64, coords_raw, npts_raw, pillars, lane, np, xc, yc, pt);

    while (p < P) {
        // ---- capture current, issue prefetch for next ----
        const int cp = p, cnp = np;
        const float cxc = xc, cyc = yc;
        const float4 cpt = pt;
        p += stride;
        if (p < P) load_pillar(p, is64, coords_raw, npts_raw, pillars, lane, np, xc, yc, pt);

        // ---- empty pillar: output all NEGV, skip compute (warp-uniform) ----
        if (cnp == 0) {
            *(float2*)(out + (size_t)cp * 64 + 2 * lane) = make_float2(NEGV, NEGV);
            continue;
        }
        const bool big = (cnp > 16);  // warp-uniform: rows 16..31 live?

        // ---- zmean ----
        float zs = (lane < cnp) ? cpt.z : 0.f;
#pragma unroll
        for (int o = 16; o; o >>= 1) zs += __shfl_xor_sync(0xffffffffu, zs, o);
        const float zm = zs / (float)cnp;

        // ---- feat row (fp16): [x,y,z,r,xc,yc,zm,1] ----
        *myfeat = make_uint4(pkf(cpt.x, cpt.y), pkf(cpt.z, cpt.w),
                             pkf(cxc, cyc), pkf(zm, 1.0f));
        __syncwarp();
        unsigned A1[4];
        ldm4(A1, featAddr);
        __syncwarp();

        const bool v0 = (rbase < cnp), v1 = (rbase + 8 < cnp);
        const bool v2 = (rbase + 16 < cnp), v3 = (rbase + 24 < cnp);

        if (big) {
            // ---- layer 1, both m halves ----
            unsigned A2[2][4][4];
#pragma unroll
            for (int mt = 0; mt < 2; mt++)
#pragma unroll
                for (int hh = 0; hh < 2; hh++)
#pragma unroll
                    for (int nt = 0; nt < 4; nt++) {
                        float C1[4];
                        mma_k8_z(C1, &A1[mt * 2], W1B[hh * 4 + nt]);
                        int s = hh * 2 + (nt >> 1), sel = nt & 1;
                        A2[mt][s][2 * sel] = pkf(fmaxf(C1[0], 0.f), fmaxf(C1[1], 0.f));
                        A2[mt][s][2 * sel + 1] = pkf(fmaxf(C1[2], 0.f), fmaxf(C1[3], 0.f));
                    }
            // ---- layer 2, fused mt loops sharing B loads ----
#pragma unroll
            for (int hh2 = 0; hh2 < 2; hh2++) {
                float C2a[4][4], C2b[4][4];
#pragma unroll
                for (int nt = 0; nt < 4; nt++) {
                    uint2 b = w2p[((hh2 * 4 + nt) * 4) * 32];
                    mma_f16_z(C2a[nt], A2[0][0], b.x, b.y);
                    mma_f16_z(C2b[nt], A2[1][0], b.x, b.y);
                }
#pragma unroll
                for (int ks = 1; ks < 4; ks++)
#pragma unroll
                    for (int nt = 0; nt < 4; nt++) {
                        uint2 b = w2p[((hh2 * 4 + nt) * 4 + ks) * 32];
                        mma_f16(C2a[nt], A2[0][ks], b.x, b.y);
                        mma_f16(C2b[nt], A2[1][ks], b.x, b.y);
                    }
                epilogue<true>(C2a, C2b, v0, v1, v2, v3, lane, hh2, s_b2p, out, cp);
            }
        } else {
            // ---- layer 1, lower m half only ----
            unsigned A2[4][4];
#pragma unroll
            for (int hh = 0; hh < 2; hh++)
#pragma unroll
                for (int nt = 0; nt < 4; nt++) {
                    float C1[4];
                    mma_k8_z(C1, &A1[0], W1B[hh * 4 + nt]);
                    int s = hh * 2 + (nt >> 1), sel = nt & 1;
                    A2[s][2 * sel] = pkf(fmaxf(C1[0], 0.f), fmaxf(C1[1], 0.f));
                    A2[s][2 * sel + 1] = pkf(fmaxf(C1[2], 0.f), fmaxf(C1[3], 0.f));
                }
            // ---- layer 2, single m half ----
#pragma unroll
            for (int hh2 = 0; hh2 < 2; hh2++) {
                float C2a[4][4];
#pragma unroll
                for (int nt = 0; nt < 4; nt++) {
                    uint2 b = w2p[((hh2 * 4 + nt) * 4) * 32];
                    mma_f16_z(C2a[nt], A2[0], b.x, b.y);
                }
#pragma unroll
                for (int ks = 1; ks < 4; ks++)
#pragma unroll
                    for (int nt = 0; nt < 4; nt++) {
                        uint2 b = w2p[((hh2 * 4 + nt) * 4 + ks) * 32];
                        mma_f16(C2a[nt], A2[ks], b.x, b.y);
                    }
                epilogue<false>(C2a, C2a, v0, v1, v2, v3, lane, hh2, s_b2p, out, cp);
            }
        }
        __syncwarp();  // protect s_feat reuse across iterations
    }
}

extern "C" void kernel_launch(void* const* d_in, const int* in_sizes, int n_in,
                              void* d_out, int out_size) {
    const float* pillars = (const float*)d_in[0];
    const void*  coords  = d_in[1];
    const void*  npts    = d_in[2];
    const float* W1 = (const float*)d_in[3];
    const float* b1 = (const float*)d_in[4];
    const float* g1 = (const float*)d_in[5];
    const float* be1 = (const float*)d_in[6];
    const float* m1 = (const float*)d_in[7];
    const float* v1 = (const float*)d_in[8];
    const float* W2 = (const float*)d_in[9];
    const float* b2 = (const float*)d_in[10];
    const float* g2 = (const float*)d_in[11];
    const float* be2 = (const float*)d_in[12];
    const float* m2 = (const float*)d_in[13];
    const float* v2 = (const float*)d_in[14];

    int P = in_sizes[0] / 128;
    int n_words = 2 * P < 4096 ? 2 * P : 4096;

    prep_kernel<<<1, 128>>>(W1, b1, g1, be1, m1, v1, W2, b2, g2, be2, m2, v2,
                            (const unsigned*)coords, n_words);

    int grid = 4 * 152;
    int need = (P + 3) / 4;
    if (grid > need) grid = need;
    if (grid < 1) grid = 1;
    pfn_main<<<grid, 128>>>((const float4*)pillars, coords, npts, (float*)d_out, P);
}